// round 16
// baseline (speedup 1.0000x reference)
#include <cuda_runtime.h>
#include <cstdint>

#define kB    32768
#define kT    276
#define kK    4416
#define kN    276

__device__ float g_h[(size_t)kB * kK];   // [B, T*2H] activations (tf32-rounded)
__device__ float g_w[(size_t)kN * kK];   // Wfc, tf32-rounded

__device__ __forceinline__ float rna(float f) {
    uint32_t u; asm("cvt.rna.tf32.f32 %0, %1;" : "=r"(u) : "f"(f));
    return __uint_as_float(u);
}

// ---------------- Phase 1: bidirectional LSTM ----------------
// Dot products via fma.rn.f32x2 across H-lane pairs; scalar transcendentals.
// __launch_bounds__(256, 2): cap 128 regs -> 2 CTAs/SM -> single wave of 256 CTAs.
__device__ __forceinline__ float sigm(float x) {
    return __fdividef(1.0f, 1.0f + __expf(-x));
}
__device__ __forceinline__ float tanh_acc(float x) {
    float e = __expf(-2.0f * fabsf(x));
    return copysignf(__fdividef(1.0f - e, 1.0f + e), x);
}
__device__ __forceinline__ unsigned long long PK2(float lo, float hi) {
    unsigned long long r;
    asm("mov.b64 %0, {%1,%2};" : "=l"(r) : "f"(lo), "f"(hi));
    return r;
}
__device__ __forceinline__ void UPK2(unsigned long long v, float& lo, float& hi) {
    asm("mov.b64 {%0,%1}, %2;" : "=f"(lo), "=f"(hi) : "l"(v));
}
__device__ __forceinline__ unsigned long long FMA2(unsigned long long a,
                                                   unsigned long long b,
                                                   unsigned long long c) {
    unsigned long long d;
    asm("fma.rn.f32x2 %0, %1, %2, %3;" : "=l"(d) : "l"(a), "l"(b), "l"(c));
    return d;
}

__global__ void __launch_bounds__(256, 2) lstm_k(
    const float* __restrict__ x,
    const float* __restrict__ Wih_f, const float* __restrict__ Whh_f,
    const float* __restrict__ bih_f, const float* __restrict__ bhh_f,
    const float* __restrict__ Wih_b, const float* __restrict__ Whh_b,
    const float* __restrict__ bih_b, const float* __restrict__ bhh_b)
{
    // packed across H-lane pairs: lanes (2p, 2p+1) of gate G
    __shared__ unsigned long long s_whh2[128];  // (G*4+p)*8+j
    __shared__ unsigned long long s_wih2[32];   // (G*4+p)*2+k
    __shared__ unsigned long long s_b2[16];     // G*4+p

    const int tid = threadIdx.x;
    const int dir = blockIdx.y;
    const float* Whh = dir ? Whh_b : Whh_f;
    const float* Wih = dir ? Wih_b : Wih_f;
    const float* bih = dir ? bih_b : bih_f;
    const float* bhh = dir ? bhh_b : bhh_f;

    if (tid < 128) {
        int G = tid >> 5, p = (tid >> 3) & 3, j = tid & 7;
        s_whh2[(G * 4 + p) * 8 + j] =
            PK2(Whh[(G * 8 + 2 * p) * 8 + j], Whh[(G * 8 + 2 * p + 1) * 8 + j]);
    }
    if (tid < 32) {
        int G = tid >> 3, p = (tid >> 1) & 3, k = tid & 1;
        s_wih2[(G * 4 + p) * 2 + k] =
            PK2(Wih[(G * 8 + 2 * p) * 2 + k], Wih[(G * 8 + 2 * p + 1) * 2 + k]);
    }
    if (tid < 16) {
        int G = tid >> 2, p = tid & 3;
        int l0 = G * 8 + 2 * p;
        s_b2[G * 4 + p] = PK2(bih[l0] + bhh[l0], bih[l0 + 1] + bhh[l0 + 1]);
    }
    __syncthreads();

    const int b = blockIdx.x * 256 + tid;
    const float2* xp = reinterpret_cast<const float2*>(x) + (size_t)b * kT;
    int t = dir ? (kT - 1) : 0;
    const int dt = dir ? -1 : 1;
    float* hb = g_h + (size_t)b * kK + dir * 8;

    float h[8], c[8];
#pragma unroll
    for (int l = 0; l < 8; l++) { h[l] = 0.f; c[l] = 0.f; }

    float2 xv = xp[t];
    for (int s = 0; s < kT; ++s) {
        float2 xnext = xv;
        if (s + 1 < kT) xnext = xp[t + dt];

        unsigned long long hd[8];
#pragma unroll
        for (int j = 0; j < 8; j++) hd[j] = PK2(h[j], h[j]);
        const unsigned long long xxd = PK2(xv.x, xv.x);
        const unsigned long long xyd = PK2(xv.y, xv.y);

        float hn[8];
#pragma unroll
        for (int p = 0; p < 4; p++) {
            unsigned long long aI = FMA2(xyd, s_wih2[(0 * 4 + p) * 2 + 1], s_b2[0 * 4 + p]);
            unsigned long long aF = FMA2(xyd, s_wih2[(1 * 4 + p) * 2 + 1], s_b2[1 * 4 + p]);
            unsigned long long aG = FMA2(xyd, s_wih2[(2 * 4 + p) * 2 + 1], s_b2[2 * 4 + p]);
            unsigned long long aO = FMA2(xyd, s_wih2[(3 * 4 + p) * 2 + 1], s_b2[3 * 4 + p]);
            aI = FMA2(xxd, s_wih2[(0 * 4 + p) * 2], aI);
            aF = FMA2(xxd, s_wih2[(1 * 4 + p) * 2], aF);
            aG = FMA2(xxd, s_wih2[(2 * 4 + p) * 2], aG);
            aO = FMA2(xxd, s_wih2[(3 * 4 + p) * 2], aO);
#pragma unroll
            for (int j = 0; j < 8; j++) {
                unsigned long long hj = hd[j];
                aI = FMA2(hj, s_whh2[(0 * 4 + p) * 8 + j], aI);
                aF = FMA2(hj, s_whh2[(1 * 4 + p) * 8 + j], aF);
                aG = FMA2(hj, s_whh2[(2 * 4 + p) * 8 + j], aG);
                aO = FMA2(hj, s_whh2[(3 * 4 + p) * 8 + j], aO);
            }
            float ai0, ai1, af0, af1, ag0, ag1, ao0, ao1;
            UPK2(aI, ai0, ai1); UPK2(aF, af0, af1);
            UPK2(aG, ag0, ag1); UPK2(aO, ao0, ao1);

            {
                const int l = 2 * p;
                float cn = fmaf(sigm(af0), c[l], sigm(ai0) * tanh_acc(ag0));
                c[l] = cn;
                hn[l] = sigm(ao0) * tanh_acc(cn);
            }
            {
                const int l = 2 * p + 1;
                float cn = fmaf(sigm(af1), c[l], sigm(ai1) * tanh_acc(ag1));
                c[l] = cn;
                hn[l] = sigm(ao1) * tanh_acc(cn);
            }
        }
#pragma unroll
        for (int l = 0; l < 8; l++) h[l] = hn[l];

        float4* dst = reinterpret_cast<float4*>(hb + (size_t)t * 16);
        dst[0] = make_float4(rna(hn[0]), rna(hn[1]), rna(hn[2]), rna(hn[3]));
        dst[1] = make_float4(rna(hn[4]), rna(hn[5]), rna(hn[6]), rna(hn[7]));
        t += dt;
        xv = xnext;
    }
}

// ---------------- Wfc pre-rounding ----------------
__global__ void __launch_bounds__(256) wprep_k(const float* __restrict__ w) {
    int i = blockIdx.x * 256 + threadIdx.x;
    if (i < kN * kK / 4) {
        float4 v = reinterpret_cast<const float4*>(w)[i];
        v.x = rna(v.x); v.y = rna(v.y); v.z = rna(v.z); v.w = rna(v.w);
        reinterpret_cast<float4*>(g_w)[i] = v;
    }
}

// ---------------- Phase 2: FC GEMM, mma.sync tf32, 3-stage pipeline (unchanged) ----------------
#define ASTR 36
#define STGF (416 * ASTR)
#define BOFF (128 * ASTR)
#define NSTG 138
#define FC_SMEM (3 * STGF * 4)

__device__ __forceinline__ uint32_t smem_u32(const void* p) {
    uint32_t a;
    asm("{ .reg .u64 t; cvta.to.shared.u64 t, %1; cvt.u32.u64 %0, t; }" : "=r"(a) : "l"(p));
    return a;
}
__device__ __forceinline__ void cpa16(uint32_t d, const void* s) {
    asm volatile("cp.async.cg.shared.global [%0], [%1], 16;" :: "r"(d), "l"(s));
}
__device__ __forceinline__ void mma_tf32(float* d, const uint32_t* a, const uint32_t* b) {
    asm volatile(
        "mma.sync.aligned.m16n8k8.row.col.f32.tf32.tf32.f32 "
        "{%0,%1,%2,%3}, {%4,%5,%6,%7}, {%8,%9}, {%0,%1,%2,%3};"
        : "+f"(d[0]), "+f"(d[1]), "+f"(d[2]), "+f"(d[3])
        : "r"(a[0]), "r"(a[1]), "r"(a[2]), "r"(a[3]), "r"(b[0]), "r"(b[1]));
}

__global__ void __launch_bounds__(256, 1) fc_k(const float* __restrict__ bfc,
                                               float* __restrict__ out)
{
    extern __shared__ float sm[];

    const int tid = threadIdx.x;
    const int wid = tid >> 5, lid = tid & 31;
    const int wm = (wid & 1) * 64;
    const int wn = (wid >> 1) * 72;
    const int r  = lid >> 2, cc = lid & 3;
    const size_t m0 = (size_t)blockIdx.x * 128;

    for (int i = tid; i < 3 * 12 * ASTR; i += 256) {
        int stg = i / (12 * ASTR), rem = i % (12 * ASTR);
        sm[stg * STGF + BOFF + 276 * ASTR + rem] = 0.f;
    }
    __syncthreads();

    auto loadST = [&](int st, int stg) {
        const uint32_t base = smem_u32(sm + stg * STGF);
        const float* srcA = g_h + m0 * kK + st * 32;
#pragma unroll
        for (int i = 0; i < 4; i++) {
            int seg = tid + i * 256;
            int row = seg >> 3, ks = seg & 7;
            cpa16(base + (row * ASTR + ks * 4) * 4, srcA + (size_t)row * kK + ks * 4);
        }
        const float* srcB = g_w + st * 32;
#pragma unroll
        for (int i = 0; i < 9; i++) {
            int seg = tid + i * 256;
            if (seg < kN * 8) {
                int row = seg >> 3, ks = seg & 7;
                cpa16(base + (BOFF + row * ASTR + ks * 4) * 4,
                      srcB + (size_t)row * kK + ks * 4);
            }
        }
    };

    float acc[4][9][4];
#pragma unroll
    for (int mf = 0; mf < 4; mf++)
#pragma unroll
        for (int nf = 0; nf < 9; nf++)
#pragma unroll
            for (int q = 0; q < 4; q++) acc[mf][nf][q] = 0.f;

    loadST(0, 0);
    asm volatile("cp.async.commit_group;");
    loadST(1, 1);
    asm volatile("cp.async.commit_group;");

    for (int s = 0; s < NSTG; s++) {
        const int buf = s % 3;
        if (s + 2 < NSTG) asm volatile("cp.async.wait_group 1;");
        else              asm volatile("cp.async.wait_group 0;");
        __syncthreads();

        const float* A_ = sm + buf * STGF + (wm + r) * ASTR;
        const float* B_ = sm + buf * STGF + BOFF + (wn + r) * ASTR;
#pragma unroll
        for (int kk = 0; kk < 4; kk++) {
            const int k0 = kk * 8 + cc;
            uint32_t a[4][4], bfr[9][2];
#pragma unroll
            for (int mf = 0; mf < 4; mf++) {
                const float* p = A_ + mf * 16 * ASTR + k0;
                a[mf][0] = __float_as_uint(p[0]);
                a[mf][1] = __float_as_uint(p[8 * ASTR]);
                a[mf][2] = __float_as_uint(p[4]);
                a[mf][3] = __float_as_uint(p[8 * ASTR + 4]);
            }
#pragma unroll
            for (int nf = 0; nf < 9; nf++) {
                const float* p = B_ + nf * 8 * ASTR + k0;
                bfr[nf][0] = __float_as_uint(p[0]);
                bfr[nf][1] = __float_as_uint(p[4]);
            }
#pragma unroll
            for (int mf = 0; mf < 4; mf++)
#pragma unroll
                for (int nf = 0; nf < 9; nf++)
                    mma_tf32(acc[mf][nf], a[mf], bfr[nf]);
        }

        if (s + 2 < NSTG) {
            loadST(s + 2, (s + 2) % 3);
            asm volatile("cp.async.commit_group;");
        }
    }

#pragma unroll
    for (int nf = 0; nf < 9; nf++) {
        const int n0 = wn + nf * 8 + cc * 2;
        if (n0 < kN) {
            const float b0 = bfc[n0], b1 = bfc[n0 + 1];
#pragma unroll
            for (int mf = 0; mf < 4; mf++) {
                const size_t mlo = m0 + wm + mf * 16 + r;
                float2 v0 = make_float2(acc[mf][nf][0] + b0, acc[mf][nf][1] + b1);
                float2 v1 = make_float2(acc[mf][nf][2] + b0, acc[mf][nf][3] + b1);
                *reinterpret_cast<float2*>(out + mlo * kN + n0)       = v0;
                *reinterpret_cast<float2*>(out + (mlo + 8) * kN + n0) = v1;
            }
        }
    }
}

extern "C" void kernel_launch(void* const* d_in, const int* in_sizes, int n_in,
                              void* d_out, int out_size) {
    const float* x     = (const float*)d_in[0];
    const float* Wih_f = (const float*)d_in[1];
    const float* Whh_f = (const float*)d_in[2];
    const float* bih_f = (const float*)d_in[3];
    const float* bhh_f = (const float*)d_in[4];
    const float* Wih_b = (const float*)d_in[5];
    const float* Whh_b = (const float*)d_in[6];
    const float* bih_b = (const float*)d_in[7];
    const float* bhh_b = (const float*)d_in[8];
    const float* Wfc   = (const float*)d_in[9];
    const float* bfc   = (const float*)d_in[10];
    float* out = (float*)d_out;

    static int smem_set = 0;
    if (!smem_set) {
        cudaFuncSetAttribute(fc_k, cudaFuncAttributeMaxDynamicSharedMemorySize, FC_SMEM);
        smem_set = 1;
    }

    lstm_k<<<dim3(kB / 256, 2), 256>>>(x, Wih_f, Whh_f, bih_f, bhh_f,
                                       Wih_b, Whh_b, bih_b, bhh_b);
    wprep_k<<<(kN * kK / 4 + 255) / 256, 256>>>(Wfc);
    fc_k<<<kB / 128, 256, FC_SMEM>>>(bfc, out);
}

// round 17
// speedup vs baseline: 1.3993x; 1.3993x over previous
#include <cuda_runtime.h>
#include <cstdint>

#define kB    32768
#define kT    276
#define kK    4416
#define kN    276

__device__ float g_h[(size_t)kB * kK];   // [B, T*2H] activations (tf32-rounded)
__device__ float g_w[(size_t)kN * kK];   // Wfc, tf32-rounded

__device__ __forceinline__ float rna(float f) {
    uint32_t u; asm("cvt.rna.tf32.f32 %0, %1;" : "=r"(u) : "f"(f));
    return __uint_as_float(u);
}

// ---------------- Phase 1: bidirectional LSTM ----------------
// FMA2 dot products; HW tanh.approx for all activations.
// i/f/o gate weights pre-scaled by 0.5 so sigmoid = 0.5*tanh(preact)+0.5.
__device__ __forceinline__ float tanha(float x) {
    float r; asm("tanh.approx.f32 %0, %1;" : "=f"(r) : "f"(x)); return r;
}
__device__ __forceinline__ unsigned long long PK2(float lo, float hi) {
    unsigned long long r;
    asm("mov.b64 %0, {%1,%2};" : "=l"(r) : "f"(lo), "f"(hi));
    return r;
}
__device__ __forceinline__ void UPK2(unsigned long long v, float& lo, float& hi) {
    asm("mov.b64 {%0,%1}, %2;" : "=f"(lo), "=f"(hi) : "l"(v));
}
__device__ __forceinline__ unsigned long long FMA2(unsigned long long a,
                                                   unsigned long long b,
                                                   unsigned long long c) {
    unsigned long long d;
    asm("fma.rn.f32x2 %0, %1, %2, %3;" : "=l"(d) : "l"(a), "l"(b), "l"(c));
    return d;
}

__global__ void __launch_bounds__(256) lstm_k(
    const float* __restrict__ x,
    const float* __restrict__ Wih_f, const float* __restrict__ Whh_f,
    const float* __restrict__ bih_f, const float* __restrict__ bhh_f,
    const float* __restrict__ Wih_b, const float* __restrict__ Whh_b,
    const float* __restrict__ bih_b, const float* __restrict__ bhh_b)
{
    // packed across H-lane pairs: lanes (2p, 2p+1) of gate G; G in {0:i,1:f,2:g,3:o}
    __shared__ unsigned long long s_whh2[128];  // (G*4+p)*8+j
    __shared__ unsigned long long s_wih2[32];   // (G*4+p)*2+k
    __shared__ unsigned long long s_b2[16];     // G*4+p

    const int tid = threadIdx.x;
    const int dir = blockIdx.y;
    const float* Whh = dir ? Whh_b : Whh_f;
    const float* Wih = dir ? Wih_b : Wih_f;
    const float* bih = dir ? bih_b : bih_f;
    const float* bhh = dir ? bhh_b : bhh_f;

    if (tid < 128) {
        int G = tid >> 5, p = (tid >> 3) & 3, j = tid & 7;
        float sc = (G == 2) ? 1.0f : 0.5f;        // halve sigmoid-gate preacts
        s_whh2[(G * 4 + p) * 8 + j] =
            PK2(sc * Whh[(G * 8 + 2 * p) * 8 + j], sc * Whh[(G * 8 + 2 * p + 1) * 8 + j]);
    }
    if (tid < 32) {
        int G = tid >> 3, p = (tid >> 1) & 3, k = tid & 1;
        float sc = (G == 2) ? 1.0f : 0.5f;
        s_wih2[(G * 4 + p) * 2 + k] =
            PK2(sc * Wih[(G * 8 + 2 * p) * 2 + k], sc * Wih[(G * 8 + 2 * p + 1) * 2 + k]);
    }
    if (tid < 16) {
        int G = tid >> 2, p = tid & 3;
        float sc = (G == 2) ? 1.0f : 0.5f;
        int l0 = G * 8 + 2 * p;
        s_b2[G * 4 + p] = PK2(sc * (bih[l0] + bhh[l0]),
                              sc * (bih[l0 + 1] + bhh[l0 + 1]));
    }
    __syncthreads();

    const int b = blockIdx.x * 256 + tid;
    const float2* xp = reinterpret_cast<const float2*>(x) + (size_t)b * kT;
    int t = dir ? (kT - 1) : 0;
    const int dt = dir ? -1 : 1;
    float* hb = g_h + (size_t)b * kK + dir * 8;

    float h[8], c[8];
#pragma unroll
    for (int l = 0; l < 8; l++) { h[l] = 0.f; c[l] = 0.f; }

    float2 xv = xp[t];
    for (int s = 0; s < kT; ++s) {
        float2 xnext = xv;
        if (s + 1 < kT) xnext = xp[t + dt];

        unsigned long long hd[8];
#pragma unroll
        for (int j = 0; j < 8; j++) hd[j] = PK2(h[j], h[j]);
        const unsigned long long xxd = PK2(xv.x, xv.x);
        const unsigned long long xyd = PK2(xv.y, xv.y);

        float hn[8];
#pragma unroll
        for (int p = 0; p < 4; p++) {
            unsigned long long aI = FMA2(xyd, s_wih2[(0 * 4 + p) * 2 + 1], s_b2[0 * 4 + p]);
            unsigned long long aF = FMA2(xyd, s_wih2[(1 * 4 + p) * 2 + 1], s_b2[1 * 4 + p]);
            unsigned long long aG = FMA2(xyd, s_wih2[(2 * 4 + p) * 2 + 1], s_b2[2 * 4 + p]);
            unsigned long long aO = FMA2(xyd, s_wih2[(3 * 4 + p) * 2 + 1], s_b2[3 * 4 + p]);
            aI = FMA2(xxd, s_wih2[(0 * 4 + p) * 2], aI);
            aF = FMA2(xxd, s_wih2[(1 * 4 + p) * 2], aF);
            aG = FMA2(xxd, s_wih2[(2 * 4 + p) * 2], aG);
            aO = FMA2(xxd, s_wih2[(3 * 4 + p) * 2], aO);
#pragma unroll
            for (int j = 0; j < 8; j++) {
                unsigned long long hj = hd[j];
                aI = FMA2(hj, s_whh2[(0 * 4 + p) * 8 + j], aI);
                aF = FMA2(hj, s_whh2[(1 * 4 + p) * 8 + j], aF);
                aG = FMA2(hj, s_whh2[(2 * 4 + p) * 8 + j], aG);
                aO = FMA2(hj, s_whh2[(3 * 4 + p) * 8 + j], aO);
            }
            float ai0, ai1, af0, af1, ag0, ag1, ao0, ao1;
            UPK2(aI, ai0, ai1); UPK2(aF, af0, af1);
            UPK2(aG, ag0, ag1); UPK2(aO, ao0, ao1);

            {
                const int l = 2 * p;
                float ig = fmaf(0.5f, tanha(ai0), 0.5f);
                float fg = fmaf(0.5f, tanha(af0), 0.5f);
                float og = fmaf(0.5f, tanha(ao0), 0.5f);
                float gg = tanha(ag0);
                float cn = fmaf(fg, c[l], ig * gg);
                c[l] = cn;
                hn[l] = og * tanha(cn);
            }
            {
                const int l = 2 * p + 1;
                float ig = fmaf(0.5f, tanha(ai1), 0.5f);
                float fg = fmaf(0.5f, tanha(af1), 0.5f);
                float og = fmaf(0.5f, tanha(ao1), 0.5f);
                float gg = tanha(ag1);
                float cn = fmaf(fg, c[l], ig * gg);
                c[l] = cn;
                hn[l] = og * tanha(cn);
            }
        }
#pragma unroll
        for (int l = 0; l < 8; l++) h[l] = hn[l];

        float4* dst = reinterpret_cast<float4*>(hb + (size_t)t * 16);
        dst[0] = make_float4(rna(hn[0]), rna(hn[1]), rna(hn[2]), rna(hn[3]));
        dst[1] = make_float4(rna(hn[4]), rna(hn[5]), rna(hn[6]), rna(hn[7]));
        t += dt;
        xv = xnext;
    }
}

// ---------------- Wfc pre-rounding ----------------
__global__ void __launch_bounds__(256) wprep_k(const float* __restrict__ w) {
    int i = blockIdx.x * 256 + threadIdx.x;
    if (i < kN * kK / 4) {
        float4 v = reinterpret_cast<const float4*>(w)[i];
        v.x = rna(v.x); v.y = rna(v.y); v.z = rna(v.z); v.w = rna(v.w);
        reinterpret_cast<float4*>(g_w)[i] = v;
    }
}

// ---------------- Phase 2: FC GEMM, mma.sync tf32, 3-stage pipeline (unchanged) ----------------
#define ASTR 36
#define STGF (416 * ASTR)
#define BOFF (128 * ASTR)
#define NSTG 138
#define FC_SMEM (3 * STGF * 4)

__device__ __forceinline__ uint32_t smem_u32(const void* p) {
    uint32_t a;
    asm("{ .reg .u64 t; cvta.to.shared.u64 t, %1; cvt.u32.u64 %0, t; }" : "=r"(a) : "l"(p));
    return a;
}
__device__ __forceinline__ void cpa16(uint32_t d, const void* s) {
    asm volatile("cp.async.cg.shared.global [%0], [%1], 16;" :: "r"(d), "l"(s));
}
__device__ __forceinline__ void mma_tf32(float* d, const uint32_t* a, const uint32_t* b) {
    asm volatile(
        "mma.sync.aligned.m16n8k8.row.col.f32.tf32.tf32.f32 "
        "{%0,%1,%2,%3}, {%4,%5,%6,%7}, {%8,%9}, {%0,%1,%2,%3};"
        : "+f"(d[0]), "+f"(d[1]), "+f"(d[2]), "+f"(d[3])
        : "r"(a[0]), "r"(a[1]), "r"(a[2]), "r"(a[3]), "r"(b[0]), "r"(b[1]));
}

__global__ void __launch_bounds__(256, 1) fc_k(const float* __restrict__ bfc,
                                               float* __restrict__ out)
{
    extern __shared__ float sm[];

    const int tid = threadIdx.x;
    const int wid = tid >> 5, lid = tid & 31;
    const int wm = (wid & 1) * 64;
    const int wn = (wid >> 1) * 72;
    const int r  = lid >> 2, cc = lid & 3;
    const size_t m0 = (size_t)blockIdx.x * 128;

    for (int i = tid; i < 3 * 12 * ASTR; i += 256) {
        int stg = i / (12 * ASTR), rem = i % (12 * ASTR);
        sm[stg * STGF + BOFF + 276 * ASTR + rem] = 0.f;
    }
    __syncthreads();

    auto loadST = [&](int st, int stg) {
        const uint32_t base = smem_u32(sm + stg * STGF);
        const float* srcA = g_h + m0 * kK + st * 32;
#pragma unroll
        for (int i = 0; i < 4; i++) {
            int seg = tid + i * 256;
            int row = seg >> 3, ks = seg & 7;
            cpa16(base + (row * ASTR + ks * 4) * 4, srcA + (size_t)row * kK + ks * 4);
        }
        const float* srcB = g_w + st * 32;
#pragma unroll
        for (int i = 0; i < 9; i++) {
            int seg = tid + i * 256;
            if (seg < kN * 8) {
                int row = seg >> 3, ks = seg & 7;
                cpa16(base + (BOFF + row * ASTR + ks * 4) * 4,
                      srcB + (size_t)row * kK + ks * 4);
            }
        }
    };

    float acc[4][9][4];
#pragma unroll
    for (int mf = 0; mf < 4; mf++)
#pragma unroll
        for (int nf = 0; nf < 9; nf++)
#pragma unroll
            for (int q = 0; q < 4; q++) acc[mf][nf][q] = 0.f;

    loadST(0, 0);
    asm volatile("cp.async.commit_group;");
    loadST(1, 1);
    asm volatile("cp.async.commit_group;");

    for (int s = 0; s < NSTG; s++) {
        const int buf = s % 3;
        if (s + 2 < NSTG) asm volatile("cp.async.wait_group 1;");
        else              asm volatile("cp.async.wait_group 0;");
        __syncthreads();

        const float* A_ = sm + buf * STGF + (wm + r) * ASTR;
        const float* B_ = sm + buf * STGF + BOFF + (wn + r) * ASTR;
#pragma unroll
        for (int kk = 0; kk < 4; kk++) {
            const int k0 = kk * 8 + cc;
            uint32_t a[4][4], bfr[9][2];
#pragma unroll
            for (int mf = 0; mf < 4; mf++) {
                const float* p = A_ + mf * 16 * ASTR + k0;
                a[mf][0] = __float_as_uint(p[0]);
                a[mf][1] = __float_as_uint(p[8 * ASTR]);
                a[mf][2] = __float_as_uint(p[4]);
                a[mf][3] = __float_as_uint(p[8 * ASTR + 4]);
            }
#pragma unroll
            for (int nf = 0; nf < 9; nf++) {
                const float* p = B_ + nf * 8 * ASTR + k0;
                bfr[nf][0] = __float_as_uint(p[0]);
                bfr[nf][1] = __float_as_uint(p[4]);
            }
#pragma unroll
            for (int mf = 0; mf < 4; mf++)
#pragma unroll
                for (int nf = 0; nf < 9; nf++)
                    mma_tf32(acc[mf][nf], a[mf], bfr[nf]);
        }

        if (s + 2 < NSTG) {
            loadST(s + 2, (s + 2) % 3);
            asm volatile("cp.async.commit_group;");
        }
    }

#pragma unroll
    for (int nf = 0; nf < 9; nf++) {
        const int n0 = wn + nf * 8 + cc * 2;
        if (n0 < kN) {
            const float b0 = bfc[n0], b1 = bfc[n0 + 1];
#pragma unroll
            for (int mf = 0; mf < 4; mf++) {
                const size_t mlo = m0 + wm + mf * 16 + r;
                float2 v0 = make_float2(acc[mf][nf][0] + b0, acc[mf][nf][1] + b1);
                float2 v1 = make_float2(acc[mf][nf][2] + b0, acc[mf][nf][3] + b1);
                *reinterpret_cast<float2*>(out + mlo * kN + n0)       = v0;
                *reinterpret_cast<float2*>(out + (mlo + 8) * kN + n0) = v1;
            }
        }
    }
}

extern "C" void kernel_launch(void* const* d_in, const int* in_sizes, int n_in,
                              void* d_out, int out_size) {
    const float* x     = (const float*)d_in[0];
    const float* Wih_f = (const float*)d_in[1];
    const float* Whh_f = (const float*)d_in[2];
    const float* bih_f = (const float*)d_in[3];
    const float* bhh_f = (const float*)d_in[4];
    const float* Wih_b = (const float*)d_in[5];
    const float* Whh_b = (const float*)d_in[6];
    const float* bih_b = (const float*)d_in[7];
    const float* bhh_b = (const float*)d_in[8];
    const float* Wfc   = (const float*)d_in[9];
    const float* bfc   = (const float*)d_in[10];
    float* out = (float*)d_out;

    static int smem_set = 0;
    if (!smem_set) {
        cudaFuncSetAttribute(fc_k, cudaFuncAttributeMaxDynamicSharedMemorySize, FC_SMEM);
        smem_set = 1;
    }

    lstm_k<<<dim3(kB / 256, 2), 256>>>(x, Wih_f, Whh_f, bih_f, bhh_f,
                                       Wih_b, Whh_b, bih_b, bhh_b);
    wprep_k<<<(kN * kK / 4 + 255) / 256, 256>>>(Wfc);
    fc_k<<<kB / 128, 256, FC_SMEM>>>(bfc, out);
}